// round 15
// baseline (speedup 1.0000x reference)
#include <cuda_runtime.h>

#define DIM (1u<<22)
typedef unsigned long long ull;

// Persistent scratch (allowed: __device__ globals, no allocation)
__device__ ull g_bufA[DIM];                 // packed (re,im) amplitudes
__device__ ull g_bufB[DIM];
__device__ __align__(16) ull g_Upk[4*22*8]; // per gate: 8 packed-broadcast consts
__device__ double g_acc[23];                // z[0..21], total at [22]
__device__ unsigned g_done;                 // completion counter (reset per call)

__device__ __forceinline__ int SWZ(int a){ return a ^ ((a>>4)&15); }

__device__ __forceinline__ ull fma2(ull a, ull b, ull c){
  ull d; asm("fma.rn.f32x2 %0, %1, %2, %3;" : "=l"(d) : "l"(a), "l"(b), "l"(c)); return d;
}
__device__ __forceinline__ ull mul2(ull a, ull b){
  ull d; asm("mul.rn.f32x2 %0, %1, %2;" : "=l"(d) : "l"(a), "l"(b)); return d;
}
__device__ __forceinline__ ull swp(ull a){ return (a>>32)|(a<<32); }
__device__ __forceinline__ ull packf(float lo, float hi){
  return (ull)__float_as_uint(lo) | ((ull)__float_as_uint(hi)<<32);
}
__device__ __forceinline__ float2 cxmul(float2 a, float2 b){
  return make_float2(a.x*b.x - a.y*b.y, a.x*b.y + a.y*b.x);
}

// Compute fused gate U = RZ*RY*RX for (layer, qubit); write 8 packed consts.
// Pure function of params -> bit-identical across redundant computations.
__device__ __forceinline__ void make_gate(const float* __restrict__ params,
                                          int layer, int q, ull* dst){
  const float* p = params + (layer*22 + q)*3;
  float tx = 0.5f*p[0], ty = 0.5f*p[1], tz = 0.5f*p[2];
  float cx,sx,cy,sy,cz,sz;
  sincosf(tx,&sx,&cx); sincosf(ty,&sy,&cy); sincosf(tz,&sz,&cz);
  // M = RY*RX
  float2 M00 = make_float2( cy*cx,  sy*sx);
  float2 M01 = make_float2(-sy*cx, -cy*sx);
  float2 M10 = make_float2( sy*cx, -cy*sx);
  float2 M11 = make_float2( cy*cx, -sy*sx);
  float2 em = make_float2(cz,-sz), ep = make_float2(cz,sz); // e^{-itz}, e^{+itz}
  float2 U00=cxmul(em,M00), U01=cxmul(em,M01);
  float2 U10=cxmul(ep,M10), U11=cxmul(ep,M11);
  dst[0]=packf(U00.x,U00.x); dst[1]=packf(-U00.y,U00.y);
  dst[2]=packf(U01.x,U01.x); dst[3]=packf(-U01.y,U01.y);
  dst[4]=packf(U10.x,U10.x); dst[5]=packf(-U10.y,U10.y);
  dst[6]=packf(U11.x,U11.x); dst[7]=packf(-U11.y,U11.y);
}

// Apply 2x2 gate on register-bit J over 16 register-resident packed amps.
template<int J>
__device__ __forceinline__ void gate16(ull (&r)[16], const ull* __restrict__ Up){
  const ulonglong2 q0 = ((const ulonglong2*)Up)[0];
  const ulonglong2 q1 = ((const ulonglong2*)Up)[1];
  const ulonglong2 q2 = ((const ulonglong2*)Up)[2];
  const ulonglong2 q3 = ((const ulonglong2*)Up)[3];
  const ull c00=q0.x, d00=q0.y, c01=q1.x, d01=q1.y;
  const ull c10=q2.x, d10=q2.y, c11=q3.x, d11=q3.y;
#pragma unroll
  for (int i=0;i<16;i++){
    if ((i & (1<<J)) == 0){
      const int j2 = i | (1<<J);
      const ull a=r[i], b=r[j2], as=swp(a), bs=swp(b);
      r[i]  = fma2(c00,a, fma2(d00,as, fma2(c01,b, mul2(d01,bs))));
      r[j2] = fma2(c10,a, fma2(d10,as, fma2(c11,b, mul2(d11,bs))));
    }
  }
}

// ---------------------------------------------------------------------------
// Prep: zero accumulators + completion counter, build 88 fused gates (used by
// the capped passB kernels; passA computes its gates in-kernel).
// ---------------------------------------------------------------------------
__global__ void k_prep(const float* __restrict__ params){
  int i = threadIdx.x;
  if (i == 0) g_done = 0u;
  if (i < 23) g_acc[i] = 0.0;
  if (i < 88) make_gate(params, i/22, i%22, &g_Upk[i*8]);
}

// ---------------------------------------------------------------------------
// Pass A: gates on global bits 0..11 (qubits 21..10). Tile = 4096 contiguous.
// 2-exchange structure; M1->M2 exchange is half-warp local -> __syncwarp;
// only M2->M0 needs the block barrier. Gates computed IN-KERNEL: lanes 0..11
// of every warp redundantly compute all 12 fused matrices -> shU (benign
// identical-value races), published warp-locally by the first __syncwarp.
//   M0: a=(v<<8)|t   M1: a=((t>>4)<<8)|(v<<4)|(t&15)   M2: a=(t<<4)|v
// Layers >= 2 fuse prior layer's CNOT ladder as Gray-code gather in[y^(y>>1)].
// ---------------------------------------------------------------------------
template<bool FIRST>
__global__ void __launch_bounds__(256,3) k_passA(
    const float* __restrict__ params,
    const float* __restrict__ sre, const float* __restrict__ sim,
    int layer, int dir)
{
  __shared__ ull sh[4096];
  __shared__ __align__(16) ull shU[96];   // M1(q17..14), M2(q21..18), M0(q13..10)
  const int t = threadIdx.x;
  const unsigned base = (unsigned)blockIdx.x << 12;
  const ull* in  = dir ? g_bufB : g_bufA;
  ull*       out = dir ? g_bufA : g_bufB;
  ull r[16];

  // amp loads first (LDGs overlap the gate computation below)
  const unsigned aM1b = (((unsigned)t>>4)<<8) | ((unsigned)t&15);
  if (FIRST){
#pragma unroll
    for (int v=0;v<16;v++){
      unsigned y = base | aM1b | ((unsigned)v<<4);
      r[v] = packf(sre[y], sim[y]);
    }
  } else {
#pragma unroll
    for (int v=0;v<16;v++){
      unsigned y = base | aM1b | ((unsigned)v<<4);
      unsigned x = y ^ (y>>1);          // inverse of CNOT-ladder permutation
      r[v] = in[x];
    }
  }
  // in-kernel gate computation, duplicated per warp (identical values)
  {
    const int l = t & 31;
    if (l < 12){
      const int qmapA[12] = {17,16,15,14, 21,20,19,18, 13,12,11,10};
      make_gate(params, layer, qmapA[l], &shU[l*8]);
    }
  }
  __syncwarp();   // publish shU within this warp (other warps wrote same bits)

  // stage M1: reg bit j -> a bit 4+j -> qubit 17-j
  gate16<0>(r, shU + 0);
  gate16<1>(r, shU + 8);
  gate16<2>(r, shU + 16);
  gate16<3>(r, shU + 24);
  // exchange M1 -> M2: half-warp local (amp bits 8..11 fixed at t>>4)
#pragma unroll
  for (int v=0;v<16;v++) sh[SWZ(aM1b | (v<<4))] = r[v];
  __syncwarp();
#pragma unroll
  for (int v=0;v<16;v++) r[v] = sh[SWZ((t<<4)|v)];
  // stage M2: reg bit j -> a bit j -> qubit 21-j
  gate16<0>(r, shU + 32);
  gate16<1>(r, shU + 40);
  gate16<2>(r, shU + 48);
  gate16<3>(r, shU + 56);
  // exchange M2 -> M0: block-wide (the single full barrier of the pass)
#pragma unroll
  for (int v=0;v<16;v++) sh[SWZ((t<<4)|v)] = r[v];
  __syncthreads();
#pragma unroll
  for (int v=0;v<16;v++) r[v] = sh[SWZ((v<<8)|t)];
  // stage M0: reg bit j -> a bit 8+j -> qubit 13-j
  gate16<0>(r, shU + 64);
  gate16<1>(r, shU + 72);
  gate16<2>(r, shU + 80);
  gate16<3>(r, shU + 88);
  // store in M0: coalesced
#pragma unroll
  for (int v=0;v<16;v++) out[base | ((unsigned)v<<8) | (unsigned)t] = r[v];
}

// ---------------------------------------------------------------------------
// Pass B (non-last): gates on global bits 12..21 (qubits 9..0). In-place.
// Tile local a (12b): a bits 0..1 = global bits 0..1 (payload),
// a bit k (k>=2) = global bit 10+k.  g = ((a>>2)<<12)|(blk<<2)|(a&3).
// Consts from k_prep's g_Upk (NO sincosf here - the (256,4) 64-reg cap
// spills otherwise). Per-warp duplicated staging to smem, syncwarp-published.
// ---------------------------------------------------------------------------
__global__ void __launch_bounds__(256,4) k_passB(int layer, int sel)
{
  __shared__ ull sh[4096];
  __shared__ __align__(16) ull shU[80];   // M1(q7..4), M2(q9,q8), M0(q3..0)
  const int t = threadIdx.x;
  const unsigned blk = blockIdx.x;
  ull* buf = sel ? g_bufA : g_bufB;
  const ull* Ub = &g_Upk[layer*176];
  ull r[16];

  // amp loads first
  const unsigned aM1b = (((unsigned)t>>4)<<8) | ((unsigned)t&15);
#pragma unroll
  for (int v=0;v<16;v++){
    unsigned a = aM1b | ((unsigned)v<<4);
    unsigned g = ((a>>2)<<12) | (blk<<2) | (a&3);
    r[v] = buf[g];
  }
  // per-warp duplicated const staging (identical writes, benign races)
  {
    const int l = (t & 31) * 3;
    const int qmapB[10] = {7,6,5,4, 9,8, 3,2,1,0};
    if (l   < 80) shU[l]   = Ub[qmapB[l>>3]*8 + (l&7)];
    if (l+1 < 80) shU[l+1] = Ub[qmapB[(l+1)>>3]*8 + ((l+1)&7)];
    if (l+2 < 80) shU[l+2] = Ub[qmapB[(l+2)>>3]*8 + ((l+2)&7)];
  }
  __syncwarp();

  // stage M1: reg bit j -> a bit 4+j -> global bit 14+j -> qubit 7-j
  gate16<0>(r, shU + 0);
  gate16<1>(r, shU + 8);
  gate16<2>(r, shU + 16);
  gate16<3>(r, shU + 24);
  // exchange M1 -> M2: half-warp local
#pragma unroll
  for (int v=0;v<16;v++) sh[SWZ(aM1b | (v<<4))] = r[v];
  __syncwarp();
#pragma unroll
  for (int v=0;v<16;v++) r[v] = sh[SWZ((t<<4)|v)];
  // stage M2: reg bits 2,3 -> a bits 2,3 -> global 12,13 -> qubits 9,8
  gate16<2>(r, shU + 32);
  gate16<3>(r, shU + 40);
  // exchange M2 -> M0: block-wide (single full barrier)
#pragma unroll
  for (int v=0;v<16;v++) sh[SWZ((t<<4)|v)] = r[v];
  __syncthreads();
#pragma unroll
  for (int v=0;v<16;v++) r[v] = sh[SWZ((v<<8)|t)];
  // stage M0: reg bit j -> a bit 8+j -> global bit 18+j -> qubit 3-j
  gate16<0>(r, shU + 48);
  gate16<1>(r, shU + 56);
  gate16<2>(r, shU + 64);
  gate16<3>(r, shU + 72);

  // M0 store: a=(v<<8)|t -> g = (v<<18)|((t>>2)<<12)|(blk<<2)|(t&3)
  const unsigned gbase0 = (((unsigned)t>>2)<<12) | (blk<<2) | ((unsigned)t&3);
#pragma unroll
  for (int v=0;v<16;v++) buf[gbase0 | ((unsigned)v<<18)] = r[v];
}

// ---------------------------------------------------------------------------
// Pass B (last): gate structure + fused final CNOT ladder + <Z_q> reduction,
// PLUS fused k_final: the last block to finish (completion counter) computes
// the normalized expvals and writes d_out. No separate k_final launch.
// ---------------------------------------------------------------------------
__global__ void __launch_bounds__(256,3) k_passB_last(
    int layer, int sel, float* __restrict__ outp)
{
  __shared__ ull sh[4096];
  __shared__ __align__(16) ull shU[80];
  __shared__ double sacc[23];
  __shared__ unsigned lastflag;
  const int t = threadIdx.x;
  const unsigned blk = blockIdx.x;
  ull* buf = sel ? g_bufA : g_bufB;
  const ull* Ub = &g_Upk[layer*176];
  ull r[16];

  const unsigned aM1b = (((unsigned)t>>4)<<8) | ((unsigned)t&15);
#pragma unroll
  for (int v=0;v<16;v++){
    unsigned a = aM1b | ((unsigned)v<<4);
    unsigned g = ((a>>2)<<12) | (blk<<2) | (a&3);
    r[v] = buf[g];
  }
  {
    const int l = (t & 31) * 3;
    const int qmapB[10] = {7,6,5,4, 9,8, 3,2,1,0};
    if (l   < 80) shU[l]   = Ub[qmapB[l>>3]*8 + (l&7)];
    if (l+1 < 80) shU[l+1] = Ub[qmapB[(l+1)>>3]*8 + ((l+1)&7)];
    if (l+2 < 80) shU[l+2] = Ub[qmapB[(l+2)>>3]*8 + ((l+2)&7)];
  }
  if (t < 23) sacc[t] = 0.0;   // ordered before use by the M2->M0 syncthreads
  __syncwarp();

  gate16<0>(r, shU + 0);
  gate16<1>(r, shU + 8);
  gate16<2>(r, shU + 16);
  gate16<3>(r, shU + 24);
#pragma unroll
  for (int v=0;v<16;v++) sh[SWZ(aM1b | (v<<4))] = r[v];
  __syncwarp();
#pragma unroll
  for (int v=0;v<16;v++) r[v] = sh[SWZ((t<<4)|v)];
  gate16<2>(r, shU + 32);
  gate16<3>(r, shU + 40);
#pragma unroll
  for (int v=0;v<16;v++) sh[SWZ((t<<4)|v)] = r[v];
  __syncthreads();
#pragma unroll
  for (int v=0;v<16;v++) r[v] = sh[SWZ((v<<8)|t)];
  gate16<0>(r, shU + 48);
  gate16<1>(r, shU + 56);
  gate16<2>(r, shU + 64);
  gate16<3>(r, shU + 72);

  // Fused final CNOT ladder + <Z_q> reduction.
  // r[v] lives at g = (v<<18)|((t>>2)<<12)|(blk<<2)|(t&3) (mapping M0);
  // post-ladder basis label y_p = XOR of g bits p..21 (prefix-xor).
  const unsigned gbase0 = (((unsigned)t>>2)<<12) | (blk<<2) | ((unsigned)t&3);
  float z[22];
#pragma unroll
  for (int q=0;q<22;q++) z[q] = 0.0f;
  float tot = 0.0f;
#pragma unroll
  for (int v=0;v<16;v++){
    unsigned g = gbase0 | ((unsigned)v<<18);
    unsigned y = g; y ^= y>>1; y ^= y>>2; y ^= y>>4; y ^= y>>8; y ^= y>>16;
    float re = __uint_as_float((unsigned)r[v]);
    float im = __uint_as_float((unsigned)(r[v]>>32));
    float p = re*re + im*im;
    tot += p;
#pragma unroll
    for (int q=0;q<22;q++)
      z[q] += ((y >> (21-q)) & 1u) ? -p : p;
  }
#pragma unroll
  for (int q=0;q<22;q++){
    float val = z[q];
#pragma unroll
    for (int o=16;o;o>>=1) val += __shfl_down_sync(0xffffffffu, val, o);
    if ((t & 31) == 0) atomicAdd(&sacc[q], (double)val);
  }
  {
    float val = tot;
#pragma unroll
    for (int o=16;o;o>>=1) val += __shfl_down_sync(0xffffffffu, val, o);
    if ((t & 31) == 0) atomicAdd(&sacc[22], (double)val);
  }
  __syncthreads();
  if (t < 23) atomicAdd(&g_acc[t], sacc[t]);

  // fused k_final: last block writes the output (threadFenceReduction pattern)
  __threadfence();               // release this block's g_acc atomics
  __syncthreads();
  if (t == 0){
    unsigned n = atomicAdd(&g_done, 1u);
    lastflag = (n == gridDim.x - 1u) ? 1u : 0u;
  }
  __syncthreads();
  if (lastflag && t < 22){
    // atomic reads are L2-coherent; all g_acc adds complete (counter full)
    double num = atomicAdd(&g_acc[t], 0.0);
    double den = atomicAdd(&g_acc[22], 0.0);
    outp[t] = (float)(num / den);
  }
}

extern "C" void kernel_launch(void* const* d_in, const int* in_sizes, int n_in,
                              void* d_out, int out_size)
{
  const float* params = (const float*)d_in[0];
  const float* sre    = (const float*)d_in[1];
  const float* sim    = (const float*)d_in[2];
  float* out = (float*)d_out;

  k_prep<<<1,128>>>(params);

  // Layer 1: A writes bufA (dir=1), B in-place on bufA (sel=1)
  k_passA<true ><<<1024,256>>>(params, sre, sim, 0, 1);
  k_passB<<<1024,256>>>(0, 1);
  // Layer 2: bufA -> bufB (dir=0), B on bufB (sel=0)
  k_passA<false><<<1024,256>>>(params, nullptr, nullptr, 1, 0);
  k_passB<<<1024,256>>>(1, 0);
  // Layer 3: bufB -> bufA
  k_passA<false><<<1024,256>>>(params, nullptr, nullptr, 2, 1);
  k_passB<<<1024,256>>>(2, 1);
  // Layer 4: bufA -> bufB, B fuses final ladder + reduction + output
  k_passA<false><<<1024,256>>>(params, nullptr, nullptr, 3, 0);
  k_passB_last<<<1024,256>>>(3, 0, out);
}